// round 2
// baseline (speedup 1.0000x reference)
#include <cuda_runtime.h>
#include <cstdint>

#define N_NODES 100000
#define N_EDGES 1600000
#define IN_DIM  256
#define OUT_DIM 64

// Scratch for projected features X = inputs @ W  (25.6 MB)
__device__ float g_X[(size_t)N_NODES * OUT_DIM];

// ---------------------------------------------------------------------------
// GEMM: X[N_NODES, 64] = inputs[N_NODES, 256] @ weight[256, 64]
// Block: 256 threads, 256 rows/block. Thread: 4 rows x 16 cols, packed-f32x2
// accumulators (fma.rn.f32x2 doubles the fp32 FMA issue width on sm_103a).
// Weight staged in smem (64 KB), broadcast LDS across the warp.
// ---------------------------------------------------------------------------
__global__ __launch_bounds__(256) void gemm_kernel(
    const float* __restrict__ in, const float* __restrict__ w)
{
    __shared__ float sw[IN_DIM * OUT_DIM];  // 64 KB, row-major [k][64]

    // Cooperative weight load: 16384 floats / 256 threads = 16 float4 each
    {
        const float4* wsrc = (const float4*)w;
        float4* wdst = (float4*)sw;
        #pragma unroll
        for (int i = 0; i < 16; i++)
            wdst[threadIdx.x + i * 256] = wsrc[threadIdx.x + i * 256];
    }
    __syncthreads();

    const int colg = threadIdx.x & 3;     // 4 col-groups of 16 cols
    const int rowg = threadIdx.x >> 2;    // 64 row-groups of 4 rows
    const int row0 = blockIdx.x * 256 + rowg * 4;

    // Clamp tail rows for safe loads; stores are guarded.
    int r[4];
    #pragma unroll
    for (int i = 0; i < 4; i++) {
        int rr = row0 + i;
        r[i] = rr < N_NODES ? rr : (N_NODES - 1);
    }

    const float4* inp[4];
    #pragma unroll
    for (int i = 0; i < 4; i++)
        inp[i] = (const float4*)(in + (size_t)r[i] * IN_DIM);

    unsigned long long acc[4][8];  // 4 rows x 8 f32x2 pairs (16 cols)
    #pragma unroll
    for (int i = 0; i < 4; i++)
        #pragma unroll
        for (int j = 0; j < 8; j++) acc[i][j] = 0ULL;

    #pragma unroll 2
    for (int k4 = 0; k4 < IN_DIM / 4; k4++) {
        float4 a4[4];
        #pragma unroll
        for (int i = 0; i < 4; i++) a4[i] = inp[i][k4];

        #pragma unroll
        for (int kk = 0; kk < 4; kk++) {
            const int k = k4 * 4 + kk;
            // 8 packed weight pairs for this thread's 16 columns
            const ulonglong2* wrow =
                (const ulonglong2*)(sw + k * OUT_DIM + colg * 16);
            unsigned long long wp[8];
            #pragma unroll
            for (int j = 0; j < 4; j++) {
                ulonglong2 v = wrow[j];
                wp[2 * j]     = v.x;
                wp[2 * j + 1] = v.y;
            }
            #pragma unroll
            for (int i = 0; i < 4; i++) {
                float a = (kk == 0) ? a4[i].x : (kk == 1) ? a4[i].y
                        : (kk == 2) ? a4[i].z : a4[i].w;
                unsigned long long av;
                asm("mov.b64 %0, {%1,%1};" : "=l"(av) : "f"(a));
                #pragma unroll
                for (int j = 0; j < 8; j++)
                    asm("fma.rn.f32x2 %0, %1, %2, %0;"
                        : "+l"(acc[i][j]) : "l"(av), "l"(wp[j]));
            }
        }
    }

    #pragma unroll
    for (int i = 0; i < 4; i++) {
        int rr = row0 + i;
        if (rr < N_NODES) {
            ulonglong2* dst =
                (ulonglong2*)(g_X + (size_t)rr * OUT_DIM + colg * 16);
            dst[0] = make_ulonglong2(acc[i][0], acc[i][1]);
            dst[1] = make_ulonglong2(acc[i][2], acc[i][3]);
            dst[2] = make_ulonglong2(acc[i][4], acc[i][5]);
            dst[3] = make_ulonglong2(acc[i][6], acc[i][7]);
        }
    }
}

// ---------------------------------------------------------------------------
// Zero the output (it is poisoned before each timed replay).
// ---------------------------------------------------------------------------
__global__ void zero_kernel(float4* __restrict__ out, int n4)
{
    int i = blockIdx.x * blockDim.x + threadIdx.x;
    if (i < n4) out[i] = make_float4(0.f, 0.f, 0.f, 0.f);
}

// ---------------------------------------------------------------------------
// Scatter: out[rows[e]] += X[cols[e]]  (64 floats per edge)
// 16 threads per edge, one red.global.add.v4.f32 (16B) per thread.
// edge_index is int32 (JAX default x64-disabled downcasts int64 -> int32).
// ---------------------------------------------------------------------------
__global__ __launch_bounds__(256) void scatter_kernel(
    const int* __restrict__ rows,
    const int* __restrict__ cols,
    float* __restrict__ out)
{
    int gid = blockIdx.x * blockDim.x + threadIdx.x;
    if (gid >= N_EDGES * 16) return;
    const int e = gid >> 4;
    const int c = gid & 15;

    const int dr = rows[e];
    const int sr = cols[e];

    float4 v = *(const float4*)(g_X + (size_t)sr * OUT_DIM + c * 4);
    float* dst = out + (size_t)dr * OUT_DIM + c * 4;
    asm volatile("red.global.add.v4.f32 [%0], {%1,%2,%3,%4};"
                 :: "l"(dst), "f"(v.x), "f"(v.y), "f"(v.z), "f"(v.w)
                 : "memory");
}

// ---------------------------------------------------------------------------
// Sigmoid epilogue (in place on out)
// ---------------------------------------------------------------------------
__global__ void sigmoid_kernel(float4* __restrict__ out, int n4)
{
    int i = blockIdx.x * blockDim.x + threadIdx.x;
    if (i < n4) {
        float4 v = out[i];
        v.x = 1.0f / (1.0f + __expf(-v.x));
        v.y = 1.0f / (1.0f + __expf(-v.y));
        v.z = 1.0f / (1.0f + __expf(-v.z));
        v.w = 1.0f / (1.0f + __expf(-v.w));
        out[i] = v;
    }
}

extern "C" void kernel_launch(void* const* d_in, const int* in_sizes, int n_in,
                              void* d_out, int out_size)
{
    const float* inputs = (const float*)d_in[0];   // [100000, 256] f32
    const int*   eidx   = (const int*)d_in[1];     // [2, 1600000] int32
    const float* weight = (const float*)d_in[2];   // [256, 64] f32
    float*       out    = (float*)d_out;           // [100000, 64] f32

    const int* erows = eidx;
    const int* ecols = eidx + N_EDGES;

    const int n4 = (N_NODES * OUT_DIM) / 4;  // 1.6M float4

    // out must be zeroed before atomic accumulation
    zero_kernel<<<(n4 + 255) / 256, 256>>>((float4*)out, n4);

    // X = inputs @ W
    gemm_kernel<<<(N_NODES + 255) / 256, 256>>>(inputs, weight);

    // out[r] += X[c] over edges
    const int total = N_EDGES * 16;
    scatter_kernel<<<(total + 255) / 256, 256>>>(erows, ecols, out);

    // sigmoid in place
    sigmoid_kernel<<<(n4 + 255) / 256, 256>>>((float4*)out, n4);
}